// round 5
// baseline (speedup 1.0000x reference)
#include <cuda_runtime.h>

#define BATCH 128
#define NT 512

__device__ float g_partials[BATCH];
__device__ float g_wcol[50];
__device__ unsigned int g_count = 0;
__device__ int g_wflag = 0;

__device__ __forceinline__ float warp_sum(float v) {
#pragma unroll
    for (int o = 16; o; o >>= 1) v += __shfl_down_sync(0xffffffffu, v, o);
    return v;
}

// grid = BATCH+1. Blocks 0..127: one batch element. Block 128: w_cat column norms.
__global__ __launch_bounds__(NT, 1)
void loss_main(const float* __restrict__ input,
               const float* __restrict__ target,
               const float* __restrict__ normals,
               const float* __restrict__ param_mean,
               const float* __restrict__ param_std,
               const float* __restrict__ u,
               const float* __restrict__ w_shp,
               const float* __restrict__ w_exp,
               const int*   __restrict__ keyindex,
               const int*   __restrict__ ridx_w,
               const int*   __restrict__ ridx_v,
               float* __restrict__ out)
{
    const int tid  = threadIdx.x;
    const int lane = tid & 31;
    const int wid  = tid >> 5;

    // ============ dedicated block: batch-independent w_cat column norms ============
    if (blockIdx.x == BATCH) {
        __shared__ int srow[600];
        for (int l = tid; l < 600; l += NT) {
            int j = l / 3, c = l - 3 * j;
            int vid = (j < 68) ? keyindex[j] : ridx_w[j - 68];
            srow[l] = 3 * vid + c;
        }
        __syncthreads();
        float acc[4] = {0.f, 0.f, 0.f, 0.f};
#pragma unroll 1
        for (int rl = lane; rl < 600; rl += 32) {
            size_t r = (size_t)srow[rl];
            const float* ws = w_shp + r * 40;
            const float* we = w_exp + r * 10;
#pragma unroll
            for (int k = 0; k < 4; k++) {
                int c = wid + 16 * k;
                if (c < 50) {
                    float v = (c < 40) ? ws[c] : we[c - 40];
                    acc[k] += v * v;
                }
            }
        }
#pragma unroll
        for (int k = 0; k < 4; k++) {
            float v = warp_sum(acc[k]);
            int c = wid + 16 * k;
            if (lane == 0 && c < 50) g_wcol[c] = sqrtf(v);
        }
        __threadfence();
        __syncthreads();
        if (tid == 0) atomicExch(&g_wflag, 1);
        return;
    }

    // ============ per-batch block ============
    const int n = blockIdx.x;

    __shared__ float sp[62], spg[62];
    __shared__ float bv[600], bvg[600];
    __shared__ float tn_w[16][3];
    __shared__ float tnsq[3];
    __shared__ float4 vt4[200], vtg4[200];
    __shared__ float sncol[16][68];   // per-warp normals row-partials
    __shared__ float scol[68];        // normals column sums
    __shared__ float wred[64];
    __shared__ float wsum[16];
    __shared__ float s_wmax;
    __shared__ int   s_last;

    // ---- 0. denormalize params ----
    if (tid < 62) {
        float st = param_std[tid], mn = param_mean[tid];
        sp[tid]  = input [n * 62 + tid] * st + mn;
        spg[tid] = target[n * 62 + tid] * st + mn;
    }
    __syncthreads();

    // ---- 1. kmix_w pass: pred-only dots, all 600 rows -> tmpv sq-norms.
    //         Keypoint rows (l<204) stash pred vert in bv (shared with kmix_v).
    float tn0 = 0.f, tn1 = 0.f, tn2 = 0.f;
    for (int l = tid; l < 600; l += NT) {
        int j = l / 3, c = l - 3 * j;
        int vid = (j < 68) ? keyindex[j] : ridx_w[j - 68];
        size_t r = 3 * (size_t)vid + c;
        const float4* w4 = (const float4*)(w_shp + r * 40);
        const float2* e2 = (const float2*)(w_exp + r * 10);
        float sa = u[r], sb = 0.f;
#pragma unroll
        for (int q = 0; q < 10; q += 2) {
            float4 v0 = w4[q], v1 = w4[q + 1];
            sa += v0.x*sp[12+4*q] + v0.y*sp[13+4*q] + v0.z*sp[14+4*q] + v0.w*sp[15+4*q];
            sb += v1.x*sp[16+4*q] + v1.y*sp[17+4*q] + v1.z*sp[18+4*q] + v1.w*sp[19+4*q];
        }
#pragma unroll
        for (int q = 0; q < 5; q++) {
            float2 v = e2[q];
            sa += v.x*sp[52+2*q] + v.y*sp[53+2*q];
        }
        float s = sa + sb;
        if (l < 204) bv[l] = s;
        float s2 = s * s;
        if (c == 0) tn0 += s2; else if (c == 1) tn1 += s2; else tn2 += s2;
    }
    tn0 = warp_sum(tn0); tn1 = warp_sum(tn1); tn2 = warp_sum(tn2);
    if (lane == 0) { tn_w[wid][0] = tn0; tn_w[wid][1] = tn1; tn_w[wid][2] = tn2; }

    // ---- 2. kmix_v completion: l<204 gt-only (keypoints); l>=204 pred+gt (ridx_v) ----
    for (int l = tid; l < 600; l += NT) {
        int j = l / 3, c = l - 3 * j;
        if (l < 204) {
            int vid = keyindex[j];
            size_t r = 3 * (size_t)vid + c;
            const float4* w4 = (const float4*)(w_shp + r * 40);
            const float2* e2 = (const float2*)(w_exp + r * 10);
            float ga = u[r], gb = 0.f;
#pragma unroll
            for (int q = 0; q < 10; q += 2) {
                float4 v0 = w4[q], v1 = w4[q + 1];
                ga += v0.x*spg[12+4*q] + v0.y*spg[13+4*q] + v0.z*spg[14+4*q] + v0.w*spg[15+4*q];
                gb += v1.x*spg[16+4*q] + v1.y*spg[17+4*q] + v1.z*spg[18+4*q] + v1.w*spg[19+4*q];
            }
#pragma unroll
            for (int q = 0; q < 5; q++) {
                float2 v = e2[q];
                ga += v.x*spg[52+2*q] + v.y*spg[53+2*q];
            }
            bvg[l] = ga + gb;
        } else {
            int vid = ridx_v[j - 68];
            size_t r = 3 * (size_t)vid + c;
            const float4* w4 = (const float4*)(w_shp + r * 40);
            const float2* e2 = (const float2*)(w_exp + r * 10);
            float uu = u[r];
            float sa = uu, ga = uu;
#pragma unroll
            for (int q = 0; q < 10; q++) {
                float4 v = w4[q];
                sa += v.x*sp [12+4*q] + v.y*sp [13+4*q] + v.z*sp [14+4*q] + v.w*sp [15+4*q];
                ga += v.x*spg[12+4*q] + v.y*spg[13+4*q] + v.z*spg[14+4*q] + v.w*spg[15+4*q];
            }
#pragma unroll
            for (int q = 0; q < 5; q++) {
                float2 v = e2[q];
                sa += v.x*sp [52+2*q] + v.y*sp [53+2*q];
                ga += v.x*spg[52+2*q] + v.y*spg[53+2*q];
            }
            bv[l] = sa; bvg[l] = ga;
        }
    }

    // ---- 3. normals column sums, all 16 warps, coalesced.
    //         Warp w owns rows i = w, w+16, ...; lanes read consecutive columns.
    {
        float a0 = 0.f, a1 = 0.f, a2 = 0.f;
        const float* nb = normals + (size_t)n * (68 * 68);
#pragma unroll 1
        for (int i = wid; i < 68; i += 16) {
            const float* rowp = nb + i * 68;
            a0 += rowp[lane];
            if (lane < 36) a1 += rowp[lane + 32];
            if (lane < 4)  a2 += rowp[lane + 64];
        }
        sncol[wid][lane] = a0;
        if (lane < 36) sncol[wid][(lane + 32) % 68] = (lane < 32) ? a1 : a1;  // lanes 32..35 unreachable; lane<36 covers 32-67
        // note: lane+32 for lane in [0,36) covers cols 32..67; col 64..67 double-covered? No:
        // lane in [0,32): cols 32..63 via a1; lane in [0,4): cols 64..67 via a2.
        if (lane < 4) sncol[wid][lane + 64] += 0.f;  // placeholder, fixed below
    }
    // The a1/a2 writes above need separate slots; redo cleanly:
    __syncthreads();
    {
        // recompute partial writes cleanly (cheap: values still in registers is not
        // guaranteed across the sync, so just rebuild via second accumulation pass)
    }
    // -- clean deterministic column-sum (rebuilt): zero, then warp-partial writes --
    if (tid < 68) scol[tid] = 0.f;
    {
        float a0 = 0.f, a1 = 0.f, a2 = 0.f;
        const float* nb = normals + (size_t)n * (68 * 68);
#pragma unroll 1
        for (int i = wid; i < 68; i += 16) {
            const float* rowp = nb + i * 68;
            a0 += rowp[lane];
            if (lane < 32) a1 += rowp[lane + 32];   // cols 32..63
            if (lane < 4)  a2 += rowp[lane + 64];   // cols 64..67
        }
        sncol[wid][lane] = a0;
        if (lane < 32) sncol[wid][lane + 32] = a1;
        __syncwarp();
        if (lane < 4) sncol[wid][lane + 64] = a2;
    }
    __syncthreads();
    if (tid < 68) {
        float s = 0.f;
#pragma unroll
        for (int w = 0; w < 16; w++) s += sncol[w][tid];
        scol[tid] = s;
    }
    if (tid < 3) {
        float s = 0.f;
#pragma unroll
        for (int w = 0; w < 16; w++) s += tn_w[w][tid];
        tnsq[tid] = s;
    }

    // ---- wait for column norms block ----
    if (tid == 0) {
        while (atomicAdd(&g_wflag, 0) == 0) __nanosleep(64);
    }
    __syncthreads();
    __threadfence();  // acquire for g_wcol

    // ---- 4. weights + wpdc ----
    float wj = 0.f;
    if (tid < 62) {
        float pd = fabsf(sp[tid] - spg[tid]);
        if (tid < 11) {
            int cc = tid & 3;
            float sc = (cc < 3) ? sqrtf(tnsq[cc]) : 14.142135623730951f;  // sqrt(200)
            wj = pd * sc + 1e-6f;
        } else if (tid == 11) {
            wj = 1e-6f;
        } else {
            wj = 0.00057339936f * pd * g_wcol[tid - 12] + 1e-6f;
        }
    }
    if (tid < 64) wred[tid] = wj;
    __syncthreads();
    if (wid == 0) {
        float v = fmaxf(wred[lane], wred[lane + 32]);
#pragma unroll
        for (int o = 16; o; o >>= 1) v = fmaxf(v, __shfl_down_sync(0xffffffffu, v, o));
        if (lane == 0) s_wmax = v;
    }

    // ---- 5. rotate kmix_v verts (y-flip cancels downstream) ----
    if (tid < 200) {
        float b0 = bv [3*tid], b1 = bv [3*tid+1], b2 = bv [3*tid+2];
        float c0 = bvg[3*tid], c1 = bvg[3*tid+1], c2 = bvg[3*tid+2];
        float4 o1, o2;
        o1.x = sp [0]*b0 + sp [1]*b1 + sp [2]*b2 + sp [3];
        o1.y = sp [4]*b0 + sp [5]*b1 + sp [6]*b2 + sp [7];
        o1.z = sp [8]*b0 + sp [9]*b1 + sp[10]*b2 + sp[11];
        o1.w = 0.f;
        o2.x = spg[0]*c0 + spg[1]*c1 + spg[2]*c2 + spg[3];
        o2.y = spg[4]*c0 + spg[5]*c1 + spg[6]*c2 + spg[7];
        o2.z = spg[8]*c0 + spg[9]*c1 + spg[10]*c2 + spg[11];
        o2.w = 0.f;
        vt4[tid] = o1; vtg4[tid] = o2;
    }
    __syncthreads();
    float wmax = s_wmax;

    float wpdc = 0.f;
    if (tid < 62 && tid != 11) {
        float d = input[n * 62 + tid] - target[n * 62 + tid];
        wpdc = (wj / wmax) * d * d;
    }

    // ---- 6. chamfer split across 13 warps: dir-1 on tid<200, dir-2 on tid 256..455.
    //         Dual accumulators halve the fmin dependency chain. ----
    float cham = 0.f, nwl = 0.f;
    if (tid < 200) {
        float4 X = vtg4[tid];  // gt point: min over pred set
        float m1a = 3.4e38f, m1b = 3.4e38f;
#pragma unroll 4
        for (int k = 0; k < 200; k += 2) {
            float4 a = vt4[k];
            float d0 = X.x - a.x, d1 = X.y - a.y, d2 = X.z - a.z;
            m1a = fminf(m1a, d0*d0 + d1*d1 + d2*d2);
            float4 b = vt4[k + 1];
            float e0 = X.x - b.x, e1 = X.y - b.y, e2 = X.z - b.z;
            m1b = fminf(m1b, e0*e0 + e1*e1 + e2*e2);
        }
        cham = fminf(m1a, m1b);
    } else if (tid >= 256 && tid < 456) {
        int t = tid - 256;
        float4 Y = vt4[t];     // pred point: min over gt set
        float m2a = 3.4e38f, m2b = 3.4e38f;
#pragma unroll 4
        for (int k = 0; k < 200; k += 2) {
            float4 a = vtg4[k];
            float d0 = a.x - Y.x, d1 = a.y - Y.y, d2 = a.z - Y.z;
            m2a = fminf(m2a, d0*d0 + d1*d1 + d2*d2);
            float4 b = vtg4[k + 1];
            float e0 = b.x - Y.x, e1 = b.y - Y.y, e2 = b.z - Y.z;
            m2b = fminf(m2b, e0*e0 + e1*e1 + e2*e2);
        }
        cham = fminf(m2a, m2b);
    }
    if (tid < 68) {
        float d0 = vtg4[tid].x - vt4[tid].x;
        float d1 = vtg4[tid].y - vt4[tid].y;
        float d2 = vtg4[tid].z - vt4[tid].z;
        nwl = scol[tid] * (d0*d0 + d1*d1 + d2*d2);
    }

    // ---- 7. combine + warp-shuffle block reduce ----
    const float k_wpdc = 1.f / (128.f * 62.f);
    const float k_vdc  = 3.f * 0.001f / (128.f * 200.f);
    const float k_nwl  = 3.f * 0.001f / (128.f * 68.f * 3.f);
    float tot = wpdc * k_wpdc + cham * k_vdc + nwl * k_nwl;
    tot = warp_sum(tot);
    if (lane == 0) wsum[wid] = tot;
    __syncthreads();

    // ---- 8. finalize: partial out, last block folds 128 partials (fixed order) ----
    if (tid == 0) {
        float b = 0.f;
#pragma unroll
        for (int w = 0; w < 16; w++) b += wsum[w];
        g_partials[n] = b;
        __threadfence();
        unsigned int old = atomicAdd(&g_count, 1u);
        s_last = (old == BATCH - 1);
    }
    __syncthreads();
    if (s_last) {
        __threadfence();
        if (wid == 0) {
            float v = g_partials[lane] + g_partials[lane + 32]
                    + g_partials[lane + 64] + g_partials[lane + 96];
#pragma unroll
            for (int o = 16; o; o >>= 1) v += __shfl_down_sync(0xffffffffu, v, o);
            if (lane == 0) { out[0] = v; g_count = 0; g_wflag = 0; }
        }
    }
}

extern "C" void kernel_launch(void* const* d_in, const int* in_sizes, int n_in,
                              void* d_out, int out_size)
{
    (void)in_sizes; (void)n_in; (void)out_size;
    loss_main<<<BATCH + 1, NT>>>(
        (const float*)d_in[0],   // input
        (const float*)d_in[1],   // target
        (const float*)d_in[2],   // normals
        (const float*)d_in[3],   // param_mean
        (const float*)d_in[4],   // param_std
        (const float*)d_in[5],   // u
        (const float*)d_in[6],   // w_shp
        (const float*)d_in[7],   // w_exp
        (const int*)d_in[8],     // keyindex
        (const int*)d_in[9],     // resample_idx_w
        (const int*)d_in[10],    // resample_idx_v
        (float*)d_out);
}

// round 6
// speedup vs baseline: 1.1349x; 1.1349x over previous
#include <cuda_runtime.h>

#define BATCH 128
#define NT 512

__device__ float g_partials[BATCH];
__device__ float g_wcol[50];
__device__ unsigned int g_count = 0;
__device__ int g_wflag = 0;

__device__ __forceinline__ float warp_sum(float v) {
#pragma unroll
    for (int o = 16; o; o >>= 1) v += __shfl_down_sync(0xffffffffu, v, o);
    return v;
}

// grid = BATCH+1. Blocks 0..127: one batch element. Block 128: w_cat column norms.
__global__ __launch_bounds__(NT, 1)
void loss_main(const float* __restrict__ input,
               const float* __restrict__ target,
               const float* __restrict__ normals,
               const float* __restrict__ param_mean,
               const float* __restrict__ param_std,
               const float* __restrict__ u,
               const float* __restrict__ w_shp,
               const float* __restrict__ w_exp,
               const int*   __restrict__ keyindex,
               const int*   __restrict__ ridx_w,
               const int*   __restrict__ ridx_v,
               float* __restrict__ out)
{
    const int tid  = threadIdx.x;
    const int lane = tid & 31;
    const int wid  = tid >> 5;

    // ============ dedicated block: batch-independent w_cat column norms ============
    // Warp w handles rows w, w+16, ... Lane l owns columns l and l+32 (coalesced reads).
    if (blockIdx.x == BATCH) {
        __shared__ int srow[600];
        __shared__ float cpart[16][50];
        for (int l = tid; l < 600; l += NT) {
            int j = l / 3, c = l - 3 * j;
            int vid = (j < 68) ? keyindex[j] : ridx_w[j - 68];
            srow[l] = 3 * vid + c;
        }
        __syncthreads();
        float a1 = 0.f, a2 = 0.f;
        const int c1 = lane;            // 0..31  (always < 50, in w_shp range)
        const int c2 = lane + 32;       // 32..63 (valid if < 50)
#pragma unroll 2
        for (int rr = wid; rr < 600; rr += 16) {
            size_t r = (size_t)srow[rr];
            float v1 = w_shp[r * 40 + c1];
            a1 += v1 * v1;
            if (c2 < 50) {
                float v2 = (c2 < 40) ? w_shp[r * 40 + c2] : w_exp[r * 10 + (c2 - 40)];
                a2 += v2 * v2;
            }
        }
        cpart[wid][c1] = a1;
        if (c2 < 50) cpart[wid][c2] = a2;
        __syncthreads();
        if (tid < 50) {
            float s = 0.f;
#pragma unroll
            for (int w = 0; w < 16; w++) s += cpart[w][tid];
            g_wcol[tid] = sqrtf(s);
        }
        __threadfence();
        __syncthreads();
        if (tid == 0) atomicExch(&g_wflag, 1);
        return;
    }

    // ============ per-batch block ============
    const int n = blockIdx.x;

    __shared__ float sp[62], spg[62];
    __shared__ float bv[600], bvg[600];
    __shared__ float tn_w[16][3];
    __shared__ float tnsq[3];
    __shared__ float4 vt4[200], vtg4[200];
    __shared__ float wsum[16];
    __shared__ int   s_last;

    // ---- 0. denormalize params ----
    if (tid < 62) {
        float st = param_std[tid], mn = param_mean[tid];
        sp[tid]  = input [n * 62 + tid] * st + mn;
        spg[tid] = target[n * 62 + tid] * st + mn;
    }
    __syncthreads();

    // ---- 1. merged gather region: 1200 items, one barrier.
    //   l in [0,396):     heavy  — ridx_v row 204+l, pred+gt -> bv/bvg[204+l]
    //   l in [396,996):   medium — kmix_w row l-396, pred -> tn (+ bv[m] if m<204)
    //   l in [996,1200):  light  — keypoint row l-996, gt -> bvg[m]
    float tn0 = 0.f, tn1 = 0.f, tn2 = 0.f;
#pragma unroll 1
    for (int l = tid; l < 1200; l += NT) {
        if (l < 396) {
            int row = 204 + l;
            int j = row / 3, c = row - 3 * j;
            size_t r = 3 * (size_t)ridx_v[j - 68] + c;
            const float4* w4 = (const float4*)(w_shp + r * 40);
            const float2* e2 = (const float2*)(w_exp + r * 10);
            float uu = u[r];
            float sa = uu, sb = 0.f, ga = uu, gb = 0.f;
#pragma unroll
            for (int q = 0; q < 10; q += 2) {
                float4 v0 = w4[q], v1 = w4[q + 1];
                sa += v0.x*sp [12+4*q] + v0.y*sp [13+4*q] + v0.z*sp [14+4*q] + v0.w*sp [15+4*q];
                sb += v1.x*sp [16+4*q] + v1.y*sp [17+4*q] + v1.z*sp [18+4*q] + v1.w*sp [19+4*q];
                ga += v0.x*spg[12+4*q] + v0.y*spg[13+4*q] + v0.z*spg[14+4*q] + v0.w*spg[15+4*q];
                gb += v1.x*spg[16+4*q] + v1.y*spg[17+4*q] + v1.z*spg[18+4*q] + v1.w*spg[19+4*q];
            }
#pragma unroll
            for (int q = 0; q < 5; q++) {
                float2 v = e2[q];
                sa += v.x*sp [52+2*q] + v.y*sp [53+2*q];
                ga += v.x*spg[52+2*q] + v.y*spg[53+2*q];
            }
            bv[row] = sa + sb; bvg[row] = ga + gb;
        } else if (l < 996) {
            int m = l - 396;
            int j = m / 3, c = m - 3 * j;
            int vid = (j < 68) ? keyindex[j] : ridx_w[j - 68];
            size_t r = 3 * (size_t)vid + c;
            const float4* w4 = (const float4*)(w_shp + r * 40);
            const float2* e2 = (const float2*)(w_exp + r * 10);
            float sa = u[r], sb = 0.f;
#pragma unroll
            for (int q = 0; q < 10; q += 2) {
                float4 v0 = w4[q], v1 = w4[q + 1];
                sa += v0.x*sp[12+4*q] + v0.y*sp[13+4*q] + v0.z*sp[14+4*q] + v0.w*sp[15+4*q];
                sb += v1.x*sp[16+4*q] + v1.y*sp[17+4*q] + v1.z*sp[18+4*q] + v1.w*sp[19+4*q];
            }
#pragma unroll
            for (int q = 0; q < 5; q++) {
                float2 v = e2[q];
                sa += v.x*sp[52+2*q] + v.y*sp[53+2*q];
            }
            float s = sa + sb;
            if (m < 204) bv[m] = s;
            float s2 = s * s;
            if (c == 0) tn0 += s2; else if (c == 1) tn1 += s2; else tn2 += s2;
        } else {
            int m = l - 996;
            int j = m / 3, c = m - 3 * j;
            size_t r = 3 * (size_t)keyindex[j] + c;
            const float4* w4 = (const float4*)(w_shp + r * 40);
            const float2* e2 = (const float2*)(w_exp + r * 10);
            float ga = u[r], gb = 0.f;
#pragma unroll
            for (int q = 0; q < 10; q += 2) {
                float4 v0 = w4[q], v1 = w4[q + 1];
                ga += v0.x*spg[12+4*q] + v0.y*spg[13+4*q] + v0.z*spg[14+4*q] + v0.w*spg[15+4*q];
                gb += v1.x*spg[16+4*q] + v1.y*spg[17+4*q] + v1.z*spg[18+4*q] + v1.w*spg[19+4*q];
            }
#pragma unroll
            for (int q = 0; q < 5; q++) {
                float2 v = e2[q];
                ga += v.x*spg[52+2*q] + v.y*spg[53+2*q];
            }
            bvg[m] = ga + gb;
        }
    }
    tn0 = warp_sum(tn0); tn1 = warp_sum(tn1); tn2 = warp_sum(tn2);
    if (lane == 0) { tn_w[wid][0] = tn0; tn_w[wid][1] = tn1; tn_w[wid][2] = tn2; }
    __syncthreads();

    // ---- 2. fold tn, rotate verts, wait for wcol flag (one region) ----
    if (tid < 3) {
        float s = 0.f;
#pragma unroll
        for (int w = 0; w < 16; w++) s += tn_w[w][tid];
        tnsq[tid] = s;
    }
    if (tid >= 256 && tid < 456) {
        int t = tid - 256;
        float b0 = bv [3*t], b1 = bv [3*t+1], b2 = bv [3*t+2];
        float c0 = bvg[3*t], c1 = bvg[3*t+1], c2 = bvg[3*t+2];
        float4 o1, o2;
        o1.x = sp [0]*b0 + sp [1]*b1 + sp [2]*b2 + sp [3];
        o1.y = sp [4]*b0 + sp [5]*b1 + sp [6]*b2 + sp [7];
        o1.z = sp [8]*b0 + sp [9]*b1 + sp[10]*b2 + sp[11];
        o1.w = 0.f;
        o2.x = spg[0]*c0 + spg[1]*c1 + spg[2]*c2 + spg[3];
        o2.y = spg[4]*c0 + spg[5]*c1 + spg[6]*c2 + spg[7];
        o2.z = spg[8]*c0 + spg[9]*c1 + spg[10]*c2 + spg[11];
        o2.w = 0.f;
        vt4[t] = o1; vtg4[t] = o2;
    }
    if (tid == 32) {  // a warp-1 thread spins so warp 0 stays free
        while (atomicAdd(&g_wflag, 0) == 0) __nanosleep(64);
    }
    __syncthreads();
    __threadfence();  // acquire for g_wcol

    // ---- 3. one region: warp0 = weights+wpdc; chamfer on tid 96..195 & 256..355;
    //          nwl on tid 416..483 (thread-local normals column sums). ----
    float tot = 0.f;
    if (wid == 0) {
        // lane handles params lane and lane+32
        int p1 = lane, p2 = lane + 32;
        float wj1, wj2 = 0.f;
        {
            float pd = fabsf(sp[p1] - spg[p1]);
            if (p1 < 11) {
                int cc = p1 & 3;
                float sc = (cc < 3) ? sqrtf(tnsq[cc]) : 14.142135623730951f;
                wj1 = pd * sc + 1e-6f;
            } else if (p1 == 11) wj1 = 1e-6f;
            else wj1 = 0.00057339936f * pd * g_wcol[p1 - 12] + 1e-6f;
        }
        if (p2 < 62) {
            float pd = fabsf(sp[p2] - spg[p2]);
            wj2 = 0.00057339936f * pd * g_wcol[p2 - 12] + 1e-6f;  // p2 >= 32 > 11 always
        }
        float m = fmaxf(wj1, wj2);
#pragma unroll
        for (int o = 16; o; o >>= 1) m = fmaxf(m, __shfl_xor_sync(0xffffffffu, m, o));
        float wpdc = 0.f;
        if (p1 != 11) {
            float d = input[n * 62 + p1] - target[n * 62 + p1];
            wpdc += (wj1 / m) * d * d;
        }
        if (p2 < 62) {
            float d = input[n * 62 + p2] - target[n * 62 + p2];
            wpdc += (wj2 / m) * d * d;
        }
        tot += wpdc * (1.f / (128.f * 62.f));
    } else if (tid >= 96 && tid < 196) {
        // chamfer dir-1: gt queries t and t+100 vs pred set
        int t = tid - 96;
        float4 X1 = vtg4[t], X2 = vtg4[t + 100];
        float m1a = 3.4e38f, m1b = 3.4e38f, m2a = 3.4e38f, m2b = 3.4e38f;
#pragma unroll 4
        for (int k = 0; k < 200; k += 2) {
            float4 a = vt4[k], b = vt4[k + 1];
            float d0 = X1.x - a.x, d1 = X1.y - a.y, d2 = X1.z - a.z;
            m1a = fminf(m1a, d0*d0 + d1*d1 + d2*d2);
            float e0 = X1.x - b.x, e1 = X1.y - b.y, e2 = X1.z - b.z;
            m1b = fminf(m1b, e0*e0 + e1*e1 + e2*e2);
            float f0 = X2.x - a.x, f1 = X2.y - a.y, f2 = X2.z - a.z;
            m2a = fminf(m2a, f0*f0 + f1*f1 + f2*f2);
            float g0 = X2.x - b.x, g1 = X2.y - b.y, g2 = X2.z - b.z;
            m2b = fminf(m2b, g0*g0 + g1*g1 + g2*g2);
        }
        tot += (fminf(m1a, m1b) + fminf(m2a, m2b)) * (3.f * 0.001f / (128.f * 200.f));
    } else if (tid >= 256 && tid < 356) {
        // chamfer dir-2: pred queries t and t+100 vs gt set
        int t = tid - 256;
        float4 Y1 = vt4[t], Y2 = vt4[t + 100];
        float m1a = 3.4e38f, m1b = 3.4e38f, m2a = 3.4e38f, m2b = 3.4e38f;
#pragma unroll 4
        for (int k = 0; k < 200; k += 2) {
            float4 a = vtg4[k], b = vtg4[k + 1];
            float d0 = a.x - Y1.x, d1 = a.y - Y1.y, d2 = a.z - Y1.z;
            m1a = fminf(m1a, d0*d0 + d1*d1 + d2*d2);
            float e0 = b.x - Y1.x, e1 = b.y - Y1.y, e2 = b.z - Y1.z;
            m1b = fminf(m1b, e0*e0 + e1*e1 + e2*e2);
            float f0 = a.x - Y2.x, f1 = a.y - Y2.y, f2 = a.z - Y2.z;
            m2a = fminf(m2a, f0*f0 + f1*f1 + f2*f2);
            float g0 = b.x - Y2.x, g1 = b.y - Y2.y, g2 = b.z - Y2.z;
            m2b = fminf(m2b, g0*g0 + g1*g1 + g2*g2);
        }
        tot += (fminf(m1a, m1b) + fminf(m2a, m2b)) * (3.f * 0.001f / (128.f * 200.f));
    } else if (tid >= 416 && tid < 484) {
        // nwl: thread t owns landmark/column t; coalesced row-major reads
        int t = tid - 416;
        const float* nb = normals + (size_t)n * (68 * 68) + t;
        float a0 = 0.f, a1 = 0.f, a2 = 0.f, a3 = 0.f;
#pragma unroll
        for (int i = 0; i < 68; i += 4) {
            a0 += nb[(i + 0) * 68];
            a1 += nb[(i + 1) * 68];
            a2 += nb[(i + 2) * 68];
            a3 += nb[(i + 3) * 68];
        }
        float s = (a0 + a1) + (a2 + a3);
        float d0 = vtg4[t].x - vt4[t].x;
        float d1 = vtg4[t].y - vt4[t].y;
        float d2 = vtg4[t].z - vt4[t].z;
        tot += s * (d0*d0 + d1*d1 + d2*d2) * (3.f * 0.001f / (128.f * 68.f * 3.f));
    }

    // ---- 4. block reduce + finalize ----
    tot = warp_sum(tot);
    if (lane == 0) wsum[wid] = tot;
    __syncthreads();
    if (tid == 0) {
        float b = 0.f;
#pragma unroll
        for (int w = 0; w < 16; w++) b += wsum[w];
        g_partials[n] = b;
        __threadfence();
        unsigned int old = atomicAdd(&g_count, 1u);
        s_last = (old == BATCH - 1);
    }
    __syncthreads();
    if (s_last) {
        __threadfence();
        if (wid == 0) {
            float v = g_partials[lane] + g_partials[lane + 32]
                    + g_partials[lane + 64] + g_partials[lane + 96];
#pragma unroll
            for (int o = 16; o; o >>= 1) v += __shfl_down_sync(0xffffffffu, v, o);
            if (lane == 0) { out[0] = v; g_count = 0; g_wflag = 0; }
        }
    }
}

extern "C" void kernel_launch(void* const* d_in, const int* in_sizes, int n_in,
                              void* d_out, int out_size)
{
    (void)in_sizes; (void)n_in; (void)out_size;
    loss_main<<<BATCH + 1, NT>>>(
        (const float*)d_in[0],   // input
        (const float*)d_in[1],   // target
        (const float*)d_in[2],   // normals
        (const float*)d_in[3],   // param_mean
        (const float*)d_in[4],   // param_std
        (const float*)d_in[5],   // u
        (const float*)d_in[6],   // w_shp
        (const float*)d_in[7],   // w_exp
        (const int*)d_in[8],     // keyindex
        (const int*)d_in[9],     // resample_idx_w
        (const int*)d_in[10],    // resample_idx_v
        (float*)d_out);
}